// round 13
// baseline (speedup 1.0000x reference)
#include <cuda_runtime.h>
#include <cuda_fp16.h>
#include <math.h>
#include <stdint.h>

// ---------------------------------------------------------------------------
// FPLSTM: S=512, B=128, I=H=1024.
//   pre = X @ Wx^T + bx            (SIMT fp16 mma, cp.async 3-stage, 2 CTA/SM)
//   recurrence: persistent CTAs, 2 independent groups of 64, 4 segment
//   launches of 128 steps; per-warp register LSTM state.
//   R13: NO group barriers. Per-CTA release-flag counters + per-tile acquire
//   polls of the 4 producers of that K-tile; ring-ordered K consumption
//   starting at each CTA's own column region.
// ---------------------------------------------------------------------------

namespace {
constexpr int SEQ  = 512;
constexpr int NB   = 128;
constexpr int K    = 1024;
constexpr int H    = 1024;
constexpr int NPRE = 5 * H;

constexpr int GCTA  = 64;
constexpr int GROWS = 64;
constexpr int UCOLS = 16;
constexpr int LDWW  = K / 2 + 4;     // 516 words
constexpr int BK    = 64;
constexpr int NKT   = K / BK;        // 16
constexpr int LDA   = 36;
constexpr int ABUF  = GROWS * LDA;   // 2304 words (9216 B) per stage
constexpr int NSTG  = 6;
constexpr int PD    = 5;             // prefetch depth (tiles ahead)

constexpr int OFF_W   = 0;                       // 80 rows x LDWW
constexpr int OFF_AS  = 80 * LDWW;               // 41280
constexpr int SMEM_WORDS = OFF_AS + NSTG * ABUF; // 55104 -> 220416 B

constexpr int SEGS      = 4;
constexpr int SEG_STEPS = SEQ / SEGS;            // 128

constexpr int LDA_P  = 36;
constexpr int P_STAGE = 256 * LDA_P;
constexpr int P_SMEM  = 3 * P_STAGE;             // 110592 B
constexpr int BKP    = 64;
constexpr int NKT_P  = 16;
constexpr size_t X4 = (size_t)SEQ * NB * K / 4;
constexpr size_t W4 = (size_t)NPRE * K / 4;
}

__device__ __align__(16) float  g_pre[(size_t)SEQ * NB * NPRE];
__device__ __align__(16) __half g_xh[(size_t)SEQ * NB * K];
__device__ __align__(16) __half g_wxh[(size_t)NPRE * K];
__device__ __align__(16) __half g_hh[NB * H];
__device__ __align__(16) __half g_mh[NB * H];
__device__ __align__(16) float  g_c[NB * H];
__device__ __align__(128) unsigned g_flags[2 * 64 * 32];  // 128B-padded counters

__device__ __forceinline__ uint32_t pack_h2(float x, float y) {
    __half2 h = __floats2half2_rn(x, y);
    return *reinterpret_cast<uint32_t*>(&h);
}
__device__ __forceinline__ float fast_sigmoid(float x) {
    return __fdividef(1.0f, 1.0f + __expf(-x));
}
__device__ __forceinline__ float fast_tanh(float x) {
    return 1.0f - __fdividef(2.0f, __expf(2.0f * x) + 1.0f);
}
__device__ __forceinline__ void cp16(uint32_t saddr, const void* g) {
    asm volatile("cp.async.cg.shared.global [%0], [%1], 16;\n" :: "r"(saddr), "l"(g));
}
__device__ __forceinline__ void cp_commit() { asm volatile("cp.async.commit_group;\n"); }
template <int N> __device__ __forceinline__ void cp_wait() {
    asm volatile("cp.async.wait_group %0;\n" :: "n"(N));
}
__device__ __forceinline__ void mma_f16(float* c, const uint32_t* a, const uint32_t* b) {
    asm volatile(
        "mma.sync.aligned.m16n8k16.row.col.f32.f16.f16.f32 "
        "{%0,%1,%2,%3}, {%4,%5,%6,%7}, {%8,%9}, {%0,%1,%2,%3};\n"
        : "+f"(c[0]), "+f"(c[1]), "+f"(c[2]), "+f"(c[3])
        : "r"(a[0]), "r"(a[1]), "r"(a[2]), "r"(a[3]), "r"(b[0]), "r"(b[1]));
}
__device__ __forceinline__ void poll_flag(const unsigned* fb, int idx, unsigned target) {
    const unsigned* f = fb + idx * 32;
    unsigned v;
    do {
        asm volatile("ld.acquire.gpu.global.u32 %0, [%1];"
                     : "=r"(v) : "l"(f) : "memory");
    } while (v < target);
}
__device__ __forceinline__ void flag_release(unsigned* f) {
    asm volatile("red.release.gpu.global.add.u32 [%0], %1;"
                 :: "l"(f), "r"(1u) : "memory");
}

// ---------------------------------------------------------------------------
// round_kernel: fp16-convert X and Wx; zero c state and flags
// ---------------------------------------------------------------------------
__global__ __launch_bounds__(256) void round_kernel(const float4* __restrict__ X,
                                                    const float4* __restrict__ Wx) {
    const size_t i = (size_t)blockIdx.x * 256 + threadIdx.x;
    if (i < 2 * 64 * 32) g_flags[i] = 0u;
    if (i < (size_t)(NB * H / 4))
        reinterpret_cast<float4*>(g_c)[i] = make_float4(0.f, 0.f, 0.f, 0.f);
    if (i < X4) {
        const float4 v = X[i];
        reinterpret_cast<uint2*>(g_xh)[i] = make_uint2(pack_h2(v.x, v.y), pack_h2(v.z, v.w));
    } else if (i < X4 + W4) {
        const size_t j = i - X4;
        const float4 v = Wx[j];
        reinterpret_cast<uint2*>(g_wxh)[j] = make_uint2(pack_h2(v.x, v.y), pack_h2(v.z, v.w));
    }
}

// ---------------------------------------------------------------------------
// pre_kernel: pre = Xh @ Wxh^T + bx  (R12: 2 CTA/SM)
// ---------------------------------------------------------------------------
__device__ __forceinline__ void pre_issue(uint32_t smbase, int stage,
                                          const __half* __restrict__ Asrc,
                                          const __half* __restrict__ Bsrc,
                                          int kt, int tid) {
    const uint32_t sb = smbase + (uint32_t)(stage * P_STAGE) * 4u;
    #pragma unroll
    for (int j = 0; j < 8; ++j) {
        const int i  = tid + j * 256;
        const int r  = i >> 3;
        const int ch = i & 7;
        const __half* src = (r < 128)
            ? Asrc + (size_t)r * K + kt + ch * 8
            : Bsrc + (size_t)(r - 128) * K + kt + ch * 8;
        cp16(sb + (uint32_t)(r * LDA_P + ch * 4) * 4u, src);
    }
    cp_commit();
}

__global__ __launch_bounds__(256, 2) void pre_kernel(const float* __restrict__ bx) {
    extern __shared__ uint32_t sm_u[];
    const uint32_t smbase = (uint32_t)__cvta_generic_to_shared(sm_u);
    const int tid  = threadIdx.x;
    const int lane = tid & 31;
    const int warp = tid >> 5;
    const int wm = warp >> 2;
    const int wn = warp & 3;
    const int ar = lane >> 2;
    const int aq = lane & 3;

    const __half* Asrc = g_xh  + (size_t)blockIdx.y * 128 * K;
    const __half* Bsrc = g_wxh + (size_t)blockIdx.x * 128 * K;
    float acc[4][4][4] = {};

    pre_issue(smbase, 0, Asrc, Bsrc, 0, tid);
    pre_issue(smbase, 1, Asrc, Bsrc, BKP, tid);

    #pragma unroll 1
    for (int kt = 0; kt < NKT_P; ++kt) {
        if (kt < NKT_P - 2) { cp_wait<1>(); } else { cp_wait<0>(); }
        __syncthreads();
        if (kt + 2 < NKT_P)
            pre_issue(smbase, (kt + 2) % 3, Asrc, Bsrc, (kt + 2) * BKP, tid);

        const uint32_t* buf = sm_u + (kt % 3) * P_STAGE;
        #pragma unroll
        for (int gq = 0; gq < 4; ++gq) {
            const int ac = gq * 8 + aq;
            uint32_t af[4][4], bf[4][2];
            #pragma unroll
            for (int tm = 0; tm < 4; ++tm) {
                const uint32_t* p = buf + (wm * 64 + tm * 16 + ar) * LDA_P + ac;
                af[tm][0] = p[0];
                af[tm][1] = p[8 * LDA_P];
                af[tm][2] = p[4];
                af[tm][3] = p[8 * LDA_P + 4];
            }
            #pragma unroll
            for (int tn = 0; tn < 4; ++tn) {
                const uint32_t* q = buf + (128 + wn * 32 + tn * 8 + ar) * LDA_P + ac;
                bf[tn][0] = q[0];
                bf[tn][1] = q[4];
            }
            #pragma unroll
            for (int tm = 0; tm < 4; ++tm)
                #pragma unroll
                for (int tn = 0; tn < 4; ++tn)
                    mma_f16(&acc[tm][tn][0], af[tm], bf[tn]);
        }
        __syncthreads();
    }

    #pragma unroll
    for (int tm = 0; tm < 4; ++tm)
        #pragma unroll
        for (int tn = 0; tn < 4; ++tn) {
            const int r0 = wm * 64 + tm * 16 + ar;
            const int c0 = wn * 32 + tn * 8 + aq * 2;
            #pragma unroll
            for (int j = 0; j < 4; ++j) {
                const int rr = r0 + (j >> 1) * 8;
                const int cc = c0 + (j & 1);
                const int gm = blockIdx.y * 128 + rr;
                const int gn = blockIdx.x * 128 + cc;
                g_pre[(size_t)gm * NPRE + gn] = acc[tm][tn][j] + __ldg(bx + gn);
            }
        }
}

// ---------------------------------------------------------------------------
// Persistent recurrence kernel — flag-based fine-grained sync
// ---------------------------------------------------------------------------
__device__ __forceinline__ void lstm_issueA(uint32_t smbase, int stage,
                                            const __half* __restrict__ src,
                                            int kt, int tid) {
    const uint32_t sb = smbase + (uint32_t)(OFF_AS + stage * ABUF) * 4u;
    #pragma unroll
    for (int q = 0; q < 2; ++q) {
        const int i  = tid + q * 256;
        const int r  = i >> 3;
        const int ch = i & 7;
        cp16(sb + (uint32_t)(r * LDA + ch * 4) * 4u,
             src + (size_t)r * H + kt + ch * 8);
    }
    cp_commit();
}

__global__ __launch_bounds__(256, 1) void lstm_kernel(const float* __restrict__ Wh,
                                                      const float* __restrict__ bh,
                                                      const float* __restrict__ Wum,
                                                      const float* __restrict__ bum,
                                                      float* __restrict__ out,
                                                      int t0) {
    extern __shared__ uint32_t sm_u[];
    const uint32_t smbase = (uint32_t)__cvta_generic_to_shared(sm_u);
    uint32_t* W_s = sm_u + OFF_W;

    const int tid   = threadIdx.x;
    const int lane  = tid & 31;
    const int warp  = tid >> 5;
    const int cta   = blockIdx.x;
    const int grp   = cta >> 6;
    const int jj    = cta & 63;
    const int uBase = jj * UCOLS;
    const int gRow0 = grp * GROWS;
    const int kt0   = jj >> 2;                 // ring start: own column region
    unsigned* fbase = g_flags + grp * 64 * 32;
    unsigned* fself = fbase + jj * 32;

    // weights: rows r<64: Wh[(r>>4)*H + uBase + (r&15)]; rows 64..79: Wum
    for (int i = tid; i < 80 * 512; i += 256) {
        const int row = i >> 9;
        const int w   = i & 511;
        const float* src = (row < 64)
            ? Wh  + (size_t)((row >> 4) * H + uBase + (row & 15)) * K
            : Wum + (size_t)(uBase + (row - 64)) * K;
        const float2 v = *reinterpret_cast<const float2*>(src + w * 2);
        W_s[row * LDWW + w] = pack_h2(v.x, v.y);
    }
    __syncthreads();

    const int ar = lane >> 2;
    const int aq = lane & 3;
    const int wm = warp >> 1;
    const int wn = warp & 1;
    const int colBase = uBase + wn * 8 + aq * 2;

    float bhreg[4][2];
    #pragma unroll
    for (int g = 0; g < 4; ++g)
        #pragma unroll
        for (int jb = 0; jb < 2; ++jb)
            bhreg[g][jb] = bh[g * H + colBase + jb];
    float bureg[2];
    bureg[0] = bum[colBase];
    bureg[1] = bum[colBase + 1];

    float cst[4];
    #pragma unroll
    for (int jh = 0; jh < 2; ++jh) {
        const int b = wm * 16 + ar + 8 * jh;
        const float2 cv = *reinterpret_cast<const float2*>(
            g_c + (size_t)(gRow0 + b) * H + colBase);
        cst[jh * 2]     = cv.x;
        cst[jh * 2 + 1] = cv.y;
    }

    float ig[4], og[4], fg[4];

    #pragma unroll 1
    for (int t = t0; t < t0 + SEG_STEPS; ++t) {
        const float* pre_t = g_pre + (size_t)t * NB * NPRE;

        // ================= Phase 1: all 4 gates for owned cells ==============
        {
            float2 pre2[4][2];
            #pragma unroll
            for (int g = 0; g < 4; ++g)
                #pragma unroll
                for (int jh = 0; jh < 2; ++jh) {
                    const int b = wm * 16 + ar + 8 * jh;
                    pre2[g][jh] = __ldcg(reinterpret_cast<const float2*>(
                        pre_t + (size_t)(gRow0 + b) * NPRE + g * H + colBase));
                }

            float acc[4][4] = {};
            if (t > 0) {
                const __half* hsrc = g_hh + (size_t)gRow0 * H;
                const unsigned tgt = 2u * (unsigned)t;   // hflag of step t-1
                #pragma unroll
                for (int p = 0; p < PD; ++p) {
                    const int tile = (kt0 + p) & 15;
                    if (tid < 4) poll_flag(fbase, tile * 4 + tid, tgt);
                    __syncthreads();
                    lstm_issueA(smbase, p, hsrc, tile * BK, tid);
                }
                #pragma unroll 1
                for (int i = 0; i < NKT; ++i) {
                    if (i + PD < NKT && tid < 4)
                        poll_flag(fbase, ((kt0 + i + PD) & 15) * 4 + tid, tgt);
                    if (i <= 11)      { cp_wait<4>(); }
                    else if (i == 12) { cp_wait<3>(); }
                    else if (i == 13) { cp_wait<2>(); }
                    else if (i == 14) { cp_wait<1>(); }
                    else              { cp_wait<0>(); }
                    __syncthreads();
                    if (i + PD < NKT)
                        lstm_issueA(smbase, (i + PD) % NSTG, hsrc,
                                    ((kt0 + i + PD) & 15) * BK, tid);

                    const int kt = (kt0 + i) & 15;
                    const uint32_t* cur = sm_u + OFF_AS + (i % NSTG) * ABUF;
                    #pragma unroll
                    for (int g4 = 0; g4 < 4; ++g4) {
                        const int ac = g4 * 8 + aq;
                        uint32_t af[4];
                        const uint32_t* p = cur + (wm * 16 + ar) * LDA + ac;
                        af[0] = p[0];
                        af[1] = p[8 * LDA];
                        af[2] = p[4];
                        af[3] = p[8 * LDA + 4];
                        #pragma unroll
                        for (int g = 0; g < 4; ++g) {
                            uint32_t bf[2];
                            const uint32_t* q = W_s + (g * 16 + wn * 8 + ar) * LDWW
                                              + kt * 32 + g4 * 8 + aq;
                            bf[0] = q[0];
                            bf[1] = q[4];
                            mma_f16(&acc[g][0], af, bf);
                        }
                    }
                }
            }

            float zg[4];
            #pragma unroll
            for (int j = 0; j < 4; ++j) {
                const int jb = j & 1, jh = j >> 1;
                ig[j] = fast_sigmoid(acc[0][j] + bhreg[0][jb] + (jb ? pre2[0][jh].y : pre2[0][jh].x));
                og[j] = fast_sigmoid(acc[1][j] + bhreg[1][jb] + (jb ? pre2[1][jh].y : pre2[1][jh].x));
                zg[j] = fast_sigmoid(acc[2][j] + bhreg[2][jb] + (jb ? pre2[2][jh].y : pre2[2][jh].x));
                fg[j] = fast_sigmoid(acc[3][j] + bhreg[3][jb] + (jb ? pre2[3][jh].y : pre2[3][jh].x));
            }
            #pragma unroll
            for (int jh = 0; jh < 2; ++jh) {
                const int b = wm * 16 + ar + 8 * jh;
                const float m0 = zg[jh * 2]     * fast_tanh(cst[jh * 2]);
                const float m1 = zg[jh * 2 + 1] * fast_tanh(cst[jh * 2 + 1]);
                *reinterpret_cast<uint32_t*>(
                    g_mh + (size_t)(gRow0 + b) * H + colBase) = pack_h2(m0, m1);
            }
        }
        __syncthreads();
        if (tid == 0) flag_release(fself);     // counter -> 2t+1

        // ================= Phase 2: u + state update =========================
        {
            float2 preu[2];
            #pragma unroll
            for (int jh = 0; jh < 2; ++jh) {
                const int b = wm * 16 + ar + 8 * jh;
                preu[jh] = __ldcg(reinterpret_cast<const float2*>(
                    pre_t + (size_t)(gRow0 + b) * NPRE + 4 * H + colBase));
            }

            float acc2[4] = {};
            if (t > 0) {
                const __half* msrc = g_mh + (size_t)gRow0 * H;
                const unsigned tgt = 2u * (unsigned)t + 1u;   // mflag of step t
                #pragma unroll
                for (int p = 0; p < PD; ++p) {
                    const int tile = (kt0 + p) & 15;
                    if (tid < 4) poll_flag(fbase, tile * 4 + tid, tgt);
                    __syncthreads();
                    lstm_issueA(smbase, p, msrc, tile * BK, tid);
                }
                #pragma unroll 1
                for (int i = 0; i < NKT; ++i) {
                    if (i + PD < NKT && tid < 4)
                        poll_flag(fbase, ((kt0 + i + PD) & 15) * 4 + tid, tgt);
                    if (i <= 11)      { cp_wait<4>(); }
                    else if (i == 12) { cp_wait<3>(); }
                    else if (i == 13) { cp_wait<2>(); }
                    else if (i == 14) { cp_wait<1>(); }
                    else              { cp_wait<0>(); }
                    __syncthreads();
                    if (i + PD < NKT)
                        lstm_issueA(smbase, (i + PD) % NSTG, msrc,
                                    ((kt0 + i + PD) & 15) * BK, tid);

                    const int kt = (kt0 + i) & 15;
                    const uint32_t* cur = sm_u + OFF_AS + (i % NSTG) * ABUF;
                    #pragma unroll
                    for (int g4 = 0; g4 < 4; ++g4) {
                        const int ac = g4 * 8 + aq;
                        uint32_t af[4], bf[2];
                        const uint32_t* p = cur + (wm * 16 + ar) * LDA + ac;
                        af[0] = p[0];
                        af[1] = p[8 * LDA];
                        af[2] = p[4];
                        af[3] = p[8 * LDA + 4];
                        const uint32_t* q = W_s + (64 + wn * 8 + ar) * LDWW
                                          + kt * 32 + g4 * 8 + aq;
                        bf[0] = q[0];
                        bf[1] = q[4];
                        mma_f16(acc2, af, bf);
                    }
                }
            }

            #pragma unroll
            for (int jh = 0; jh < 2; ++jh) {
                const int b = wm * 16 + ar + 8 * jh;
                const int j0 = jh * 2;
                const float u0 = fast_tanh(acc2[j0]     + bureg[0] + preu[jh].x);
                const float u1 = fast_tanh(acc2[j0 + 1] + bureg[1] + preu[jh].y);
                const float cn0 = ig[j0]     * u0 + fg[j0]     * cst[j0];
                const float cn1 = ig[j0 + 1] * u1 + fg[j0 + 1] * cst[j0 + 1];
                cst[j0]     = cn0;
                cst[j0 + 1] = cn1;
                const float hv0 = og[j0]     * fast_tanh(cn0);
                const float hv1 = og[j0 + 1] * fast_tanh(cn1);
                *reinterpret_cast<float2*>(
                    out + ((size_t)t * NB + gRow0 + b) * H + colBase) =
                    make_float2(hv0, hv1);
                *reinterpret_cast<uint32_t*>(
                    g_hh + (size_t)(gRow0 + b) * H + colBase) = pack_h2(hv0, hv1);
                if (t == SEQ - 1) {
                    float* hn = out + ((size_t)SEQ * NB + gRow0 + b) * H + colBase;
                    float* cn = hn + (size_t)NB * H;
                    *reinterpret_cast<float2*>(hn) = make_float2(hv0, hv1);
                    *reinterpret_cast<float2*>(cn) = make_float2(cn0, cn1);
                }
            }
        }
        __syncthreads();
        if (tid == 0) flag_release(fself);     // counter -> 2t+2
    }

    // persist c for next segment
    #pragma unroll
    for (int jh = 0; jh < 2; ++jh) {
        const int b = wm * 16 + ar + 8 * jh;
        *reinterpret_cast<float2*>(g_c + (size_t)(gRow0 + b) * H + colBase) =
            make_float2(cst[jh * 2], cst[jh * 2 + 1]);
    }
}

extern "C" void kernel_launch(void* const* d_in, const int* in_sizes, int n_in,
                              void* d_out, int out_size) {
    (void)in_sizes; (void)n_in; (void)out_size;
    const float* X   = (const float*)d_in[0];
    const float* Wx  = (const float*)d_in[1];
    const float* bx  = (const float*)d_in[2];
    const float* Wh  = (const float*)d_in[3];
    const float* bh  = (const float*)d_in[4];
    const float* Wum = (const float*)d_in[5];
    const float* bum = (const float*)d_in[6];
    float* out = (float*)d_out;

    static_assert(SMEM_WORDS * 4 == 220416, "lstm smem layout");
    cudaFuncSetAttribute(lstm_kernel, cudaFuncAttributeMaxDynamicSharedMemorySize,
                         SMEM_WORDS * 4);
    cudaFuncSetAttribute(pre_kernel, cudaFuncAttributeMaxDynamicSharedMemorySize,
                         P_SMEM * 4);

    const size_t total4 = X4 + W4;
    round_kernel<<<(unsigned)((total4 + 255) / 256), 256>>>(
        (const float4*)X, (const float4*)Wx);
    pre_kernel<<<dim3(NPRE / 128, (SEQ * NB) / 128), 256, P_SMEM * 4>>>(bx);
    for (int s = 0; s < SEGS; ++s) {
        lstm_kernel<<<128, 256, SMEM_WORDS * 4>>>(
            Wh, bh, Wum, bum, out, s * SEG_STEPS);
    }
}